// round 8
// baseline (speedup 1.0000x reference)
#include <cuda_runtime.h>
#include <cstdint>

#define N0 6912      // 48*48*3
#define N1 27648     // 96*96*3
#define N2 110592    // 192*192*3
#define N_TOTAL 145152
#define MAX_BOXES 100

#define NBINS 4096
#define BIN_SHIFT 20
#define POSBIN0 2048          // bin of enc(+0.0)
#define CAP 2048
#define PRE 1024
#define TARGET 1024
#define FB 142                // blocks (142*1024 = 145408 >= N_TOTAL)

#define CHUNK_BOXES 64
#define CHUNK_BYTES (CHUNK_BOXES * 85 * 4)   // 21760, multiple of 16
#define NSTAGE 4

// dynamic smem layout
#define SM_STAGES 0                           // 4 * 21760 = 87040
#define SM_MBAR   87040                       // 64 bytes (4 mbars)
#define SM_CONF   87104                       // 4096
#define SM_RAW    91200                       // 36864
#define SM_TOTAL  128064

// ---------------- scratch (device globals; zero/const static init) -------
__device__ float4 g_box[N_TOTAL];           // written only for candidates
__device__ float  g_cls[N_TOTAL];           // written only for candidates
__device__ unsigned g_encmax = 0u;
__device__ unsigned g_encmin = 0xFFFFFFFFu;
__device__ unsigned g_hist[NBINS];          // zero-init
__device__ unsigned g_ncand;                // zero-init
__device__ unsigned g_bar1, g_bar2, g_bar3; // zero-init
__device__ unsigned long long g_cand[CAP];

// order-preserving float <-> uint32 encoding
__device__ __forceinline__ unsigned fenc(float f) {
    unsigned u = __float_as_uint(f);
    return (u & 0x80000000u) ? ~u : (u | 0x80000000u);
}
__device__ __forceinline__ float fdec(unsigned k) {
    unsigned u = (k & 0x80000000u) ? (k & 0x7FFFFFFFu) : ~k;
    return __uint_as_float(u);
}

__device__ __forceinline__ const float* lvlptr(int gi,
                                               const float* g0, const float* g1,
                                               const float* g2,
                                               int& H, int& arow, int& local) {
    if (gi < N0)           { H = 48;  arow = 2; local = gi;            return g0 + (size_t)local * 85; }
    else if (gi < N0 + N1) { H = 96;  arow = 1; local = gi - N0;       return g1 + (size_t)local * 85; }
    else                   { H = 192; arow = 0; local = gi - N0 - N1;  return g2 + (size_t)local * 85; }
}

__device__ __forceinline__ uint32_t smem_u32(const void* p) {
    uint32_t a;
    asm("{ .reg .u64 t; cvta.to.shared.u64 t, %1; cvt.u32.u64 %0, t; }"
        : "=r"(a) : "l"(p));
    return a;
}

#define MBARRIER_INIT(addr, cnt) \
    asm volatile("mbarrier.init.shared.b64 [%0], %1;" :: "r"(addr), "r"(cnt) : "memory")
#define MBARRIER_EXPECT_TX(addr, bytes) \
    asm volatile("mbarrier.arrive.expect_tx.shared.b64 _, [%0], %1;" :: "r"(addr), "r"(bytes) : "memory")
#define BULK_G2S(dst, src, bytes, mbar) \
    asm volatile("cp.async.bulk.shared::cluster.global.mbarrier::complete_tx::bytes [%0], [%1], %2, [%3];" \
                 :: "r"(dst), "l"(src), "r"(bytes), "r"(mbar) : "memory")

__device__ __forceinline__ void mbar_wait(uint32_t mbar, uint32_t parity) {
    uint32_t done;
    asm volatile(
        "{\n\t.reg .pred p;\n\t"
        "mbarrier.try_wait.parity.acquire.cta.shared::cta.b64 p, [%1], %2;\n\t"
        "selp.b32 %0, 1, 0, p;\n\t}"
        : "=r"(done) : "r"(mbar), "r"(parity) : "memory");
    if (!done) {
        asm volatile(
            "{\n\t.reg .pred P1;\n\t"
            "WL_%=:\n\t"
            "mbarrier.try_wait.parity.acquire.cta.shared::cta.b64 P1, [%0], %1, 0x989680;\n\t"
            "@P1 bra.uni WD_%=;\n\t"
            "bra.uni WL_%=;\n\t"
            "WD_%=:\n\t}"
            :: "r"(mbar), "r"(parity) : "memory");
    }
}

// grid barrier: atomic arrive, volatile-poll wait
__device__ __forceinline__ void gsync(unsigned* ctr) {
    __threadfence();
    __syncthreads();
    if (threadIdx.x == 0) {
        atomicAdd(ctr, 1u);
        while (*(volatile unsigned*)ctr < FB) __nanosleep(32);
    }
    __syncthreads();
}

// register compare-exchange step for bitonic (j <= 16, via shuffle)
__device__ __forceinline__ unsigned long long cas_reg(unsigned long long v,
                                                      unsigned i, unsigned j,
                                                      unsigned k) {
    unsigned long long pv = __shfl_xor_sync(0xffffffffu, v, j);
    bool lower = (i & j) == 0u;
    bool desc  = (i & k) == 0u;
    unsigned long long mx = v > pv ? v : pv;
    unsigned long long mn = v > pv ? pv : v;
    return (lower == desc) ? mx : mn;
}

// =================== the whole pipeline in one kernel ===================
__global__ void __launch_bounds__(1024) k_all(const float* __restrict__ g0,
                                              const float* __restrict__ g1,
                                              const float* __restrict__ g2,
                                              const float* __restrict__ anch,
                                              float* __restrict__ out) {
    extern __shared__ __align__(16) char dsm[];
    char*  stages   = dsm + SM_STAGES;
    float* s_conf   = (float*)(dsm + SM_CONF);
    char*  smem_raw = dsm + SM_RAW;
    const uint32_t mbar0 = smem_u32(dsm + SM_MBAR);

    __shared__ unsigned s_thresh;
    __shared__ unsigned s_part[32];

    const int t    = threadIdx.x;
    const int b    = blockIdx.x;
    const int lane = t & 31;
    const int w    = t >> 5;
    const int gi0  = b * 1024 + t;
    const bool own = gi0 < N_TOTAL;

    // ---------------- phase A: bulk-staged streaming ----------------------
    // block handles boxes [b*1024, b*1024+nbox) in 64-box chunks.
    // Chunks never span levels (6912, 34560 are multiples of 64).
    const int nbox = min(1024, N_TOTAL - b * 1024);
    const int NC   = nbox >> 6;

    if (t == 0) {
        #pragma unroll
        for (int s = 0; s < NSTAGE; s++) MBARRIER_INIT(mbar0 + 8 * s, 1);
        asm volatile("fence.proxy.async.shared::cta;" ::: "memory");
    }
    __syncthreads();

    if (t == 0) {
        int npro = NC < NSTAGE ? NC : NSTAGE;
        for (int c = 0; c < npro; c++) {
            int H, arow, local;
            const float* src = lvlptr(b * 1024 + c * CHUNK_BOXES, g0, g1, g2, H, arow, local);
            MBARRIER_EXPECT_TX(mbar0 + 8 * c, (unsigned)CHUNK_BYTES);
            BULK_G2S(smem_u32(stages + c * CHUNK_BYTES), src, (unsigned)CHUNK_BYTES, mbar0 + 8 * c);
        }
    }

    unsigned wemax = 0u, wemin = 0xFFFFFFFFu;

    for (int c = 0; c < NC; c++) {
        const int s = c & (NSTAGE - 1);
        const unsigned p = (unsigned)(c >> 2) & 1u;
        mbar_wait(mbar0 + 8 * s, p);

        const float* sb = (const float*)(stages + s * CHUNK_BYTES);
        #pragma unroll
        for (int r = 0; r < 2; r++) {
            const int j = 2 * w + r;                      // box within chunk
            const float* f = sb + j * 85;
            float v0 = f[lane];
            float v1 = f[32 + lane];
            float v2 = (lane < 21) ? f[64 + lane] : -3.4e38f;

            float bv = (lane >= 5) ? v0 : -3.4e38f;       // cp[0..26]
            bv = fmaxf(bv, v1);                           // cp[27..58]
            bv = fmaxf(bv, v2);                           // cp[59..79]
            unsigned ebv = __reduce_max_sync(0xffffffffu, fenc(bv));
            wemax = max(wemax, ebv);
            wemin = min(wemin, ebv);
            if (lane == 4) s_conf[c * CHUNK_BOXES + j] = v0;   // obj
        }
        __syncthreads();    // all warps done with stage s before refill
        if (t == 0 && c + NSTAGE < NC) {
            int H, arow, local;
            const float* src = lvlptr(b * 1024 + (c + NSTAGE) * CHUNK_BOXES, g0, g1, g2, H, arow, local);
            MBARRIER_EXPECT_TX(mbar0 + 8 * s, (unsigned)CHUNK_BYTES);
            BULK_G2S(smem_u32(stages + s * CHUNK_BYTES), src, (unsigned)CHUNK_BYTES, mbar0 + 8 * s);
        }
    }

    // block reduce -> global atomics (wemax/wemin warp-uniform)
    unsigned* s_mx = (unsigned*)smem_raw;
    unsigned* s_mn = (unsigned*)smem_raw + 32;
    if (lane == 0) { s_mx[w] = wemax; s_mn[w] = wemin; }
    __syncthreads();
    if (t == 0) {
        unsigned mx = s_mx[0], mn = s_mn[0];
        #pragma unroll
        for (int k = 1; k < 32; k++) {
            mx = max(mx, s_mx[k]);
            mn = min(mn, s_mn[k]);
        }
        atomicMax(&g_encmax, mx);
        atomicMin(&g_encmin, mn);
    }
    __syncthreads();

    // zero smem hist, wait for all blocks (encmax/min final)
    unsigned* sh = (unsigned*)smem_raw;   // 16 KB
    #pragma unroll
    for (int k = 0; k < 4; k++) sh[t + k * 1024] = 0u;
    gsync(&g_bar1);

    // ---------------- phase B: score + histogram ----------------
    const float Mx = fdec(__ldcg(&g_encmax));
    const float Mn = fdec(__ldcg(&g_encmin));
    unsigned e = 0u;
    if (own) {
        float c = s_conf[t];
        e = fenc(fmaxf(c * Mx, c * Mn));
        atomicAdd(&sh[e >> BIN_SHIFT], 1u);
    }
    __syncthreads();
    #pragma unroll
    for (int k = 0; k < 4; k++) {
        unsigned v = sh[t + k * 1024];
        if (v) atomicAdd(&g_hist[t + k * 1024], v);
    }
    gsync(&g_bar2);

    // ---------------- phase C: threshold (warp suffix scan) --------------
    {
        unsigned c0 = __ldcg(&g_hist[POSBIN0 + 2 * t]);
        unsigned c1 = __ldcg(&g_hist[POSBIN0 + 2 * t + 1]);
        if (t == 0) s_thresh = POSBIN0;   // default: all positives qualify
        unsigned arr = c0 + c1;

        unsigned s = arr;
        #pragma unroll
        for (int off = 1; off < 32; off <<= 1) {
            unsigned v = __shfl_down_sync(0xffffffffu, s, off);
            if (lane + off < 32) s += v;
        }
        if (lane == 0) s_part[w] = s;
        __syncthreads();
        if (w == 0) {
            unsigned pv = s_part[lane];
            unsigned ps = pv;
            #pragma unroll
            for (int off = 1; off < 32; off <<= 1) {
                unsigned v = __shfl_down_sync(0xffffffffu, ps, off);
                if (lane + off < 32) ps += v;
            }
            s_part[lane] = ps - pv;       // exclusive suffix over warps
        }
        __syncthreads();
        unsigned sufInc   = s + s_part[w];
        unsigned sufAfter = sufInc - arr;
        if (sufAfter < TARGET && sufInc >= TARGET) {
            s_thresh = (sufAfter + c1 >= TARGET) ? (POSBIN0 + 2 * t + 1)
                                                 : (POSBIN0 + 2 * t);
        }
    }
    __syncthreads();
    const unsigned threshB = s_thresh;

    // ---------------- phase D: compact + candidate-only decode -----------
    if (own && (e >> BIN_SHIFT) >= threshB) {
        unsigned pos = atomicAdd(&g_ncand, 1u);
        if (pos < CAP) {
            g_cand[pos] = ((unsigned long long)e << 32) |
                          (unsigned long long)(0xFFFFFFFFu - (unsigned)gi0);

            // full decode for this candidate only (L2-hot reload)
            int H, arow, local;
            const float* p = lvlptr(gi0, g0, g1, g2, H, arow, local);
            float tx = p[0], ty = p[1], tw = p[2], th = p[3];
            float best = p[5];
            int bc = 0;
            #pragma unroll 8
            for (int c = 1; c < 80; c++) {
                float vv = p[5 + c];
                if (vv > best) { best = vv; bc = c; }
            }

            int a    = local % 3;
            int cell = local / 3;
            int cx   = cell % H;   // W == H for all levels
            int cy   = cell / H;
            float fH = (float)H;
            float fx = (tx + (float)cx) / fH;
            float fy = (ty + (float)cy) / fH;
            float ax = anch[arow * 6 + a * 2 + 0];
            float ay = anch[arow * 6 + a * 2 + 1];
            float bw = expf(tw) * ax;
            float bh = expf(th) * ay;

            g_box[gi0] = make_float4(fx - bw * 0.5f, fy - bh * 0.5f,
                                     fx + bw * 0.5f, fy + bh * 0.5f);
            g_cls[gi0] = (float)bc;
        }
    }

    // barrier 3: arrive-only; block 0 waits
    __threadfence();
    __syncthreads();
    if (t == 0) atomicAdd(&g_bar3, 1u);
    if (b != 0) return;
    if (t == 0) {
        while (*(volatile unsigned*)&g_bar3 < FB) __nanosleep(32);
    }
    __syncthreads();

    // ---------------- phase E (block 0): hybrid bitonic sort --------------
    unsigned long long* keys = (unsigned long long*)smem_raw;      // 16 KB
    float4* sbox = (float4*)(smem_raw + 16384);                    // 16 KB
    float*  scls = (float*)(smem_raw + 32768);                     // 4 KB

    const unsigned M = min(__ldcg(&g_ncand), (unsigned)CAP);
    unsigned long long a  = (t        < (int)M) ? __ldcg(&g_cand[t])        : 0ull;
    unsigned long long bk = (t + 1024 < (int)M) ? __ldcg(&g_cand[t + 1024]) : 0ull;

    #pragma unroll
    for (unsigned k = 2; k <= 32; k <<= 1) {
        #pragma unroll
        for (unsigned j = k >> 1; j > 0; j >>= 1) {
            a  = cas_reg(a,  (unsigned)t,         j, k);
            bk = cas_reg(bk, (unsigned)t + 1024u, j, k);
        }
    }
    keys[t] = a; keys[t + 1024] = bk;
    __syncthreads();

    for (unsigned k = 64; k <= CAP; k <<= 1) {
        for (unsigned j = k >> 1; j >= 32; j >>= 1) {
            #pragma unroll
            for (unsigned bb = 0; bb < 2; bb++) {
                unsigned i = (unsigned)t + bb * 1024u;
                unsigned ixj = i ^ j;
                if (ixj > i) {
                    unsigned long long x = keys[i], y = keys[ixj];
                    bool desc = ((i & k) == 0u);
                    if ((x < y) == desc) { keys[i] = y; keys[ixj] = x; }
                }
            }
            __syncthreads();
        }
        a = keys[t]; bk = keys[t + 1024];
        #pragma unroll
        for (unsigned j = 16; j > 0; j >>= 1) {
            a  = cas_reg(a,  (unsigned)t,         j, k);
            bk = cas_reg(bk, (unsigned)t + 1024u, j, k);
        }
        keys[t] = a; keys[t + 1024] = bk;
        __syncthreads();
    }

    // ---------------- phase F: prefetch top PRE boxes; zero output -------
    if (t < PRE && t < (int)M) {
        unsigned idx = 0xFFFFFFFFu - (unsigned)(keys[t] & 0xFFFFFFFFull);
        float4 bx;
        bx.x = __ldcg(&g_box[idx].x);
        bx.y = __ldcg(&g_box[idx].y);
        bx.z = __ldcg(&g_box[idx].z);
        bx.w = __ldcg(&g_box[idx].w);
        sbox[t] = bx;
        scls[t] = __ldcg(&g_cls[idx]);
    }
    if (t < 601) out[t] = 0.0f;
    __syncthreads();

    // ---------------- phase G: warp 0 greedy scan -------------------------
    if (t < 32) {
        float kx1[4], ky1[4], kx2[4], ky2[4], ka[4];
        int kept = 0;

        for (unsigned r = 0; r < M && kept < MAX_BOXES; r++) {
            unsigned long long key = keys[r];
            unsigned senc = (unsigned)(key >> 32);
            if (senc <= 0x80000000u) break;       // best remaining score <= 0

            float4 c;
            float cls;
            if (r < PRE) { c = sbox[r]; cls = scls[r]; }
            else {
                unsigned idx = 0xFFFFFFFFu - (unsigned)(key & 0xFFFFFFFFull);
                c.x = __ldcg(&g_box[idx].x);
                c.y = __ldcg(&g_box[idx].y);
                c.z = __ldcg(&g_box[idx].z);
                c.w = __ldcg(&g_box[idx].w);
                cls = __ldcg(&g_cls[idx]);
            }
            float carea = (c.z - c.x) * (c.w - c.y);

            bool conflict = false;
            #pragma unroll
            for (int q = 0; q < 4; q++) {
                if (q * 32 + lane < kept) {
                    float iw = fmaxf(fminf(kx2[q], c.z) - fmaxf(kx1[q], c.x), 0.0f);
                    float ih = fmaxf(fminf(ky2[q], c.w) - fmaxf(ky1[q], c.y), 0.0f);
                    float inter = iw * ih;
                    float iou = inter / (carea + ka[q] - inter);
                    conflict |= (iou > 0.5f);
                }
            }
            if (__ballot_sync(0xffffffffu, conflict) == 0u) {
                int s = kept;
                #pragma unroll
                for (int q = 0; q < 4; q++) {
                    if ((s >> 5) == q && lane == (s & 31)) {
                        kx1[q] = c.x; ky1[q] = c.y;
                        kx2[q] = c.z; ky2[q] = c.w;
                        ka[q]  = carea;
                    }
                }
                if (lane == 0) {
                    out[s * 4 + 0] = c.x;
                    out[s * 4 + 1] = c.y;
                    out[s * 4 + 2] = c.z;
                    out[s * 4 + 3] = c.w;
                    out[400 + s]   = fdec(senc);
                    out[500 + s]   = cls;
                }
                kept++;
            }
        }
        if (lane == 0) out[600] = (float)kept;
    }

    // ---------------- phase H: reset state for next call ------------------
    __syncthreads();
    #pragma unroll
    for (int k = 0; k < 4; k++) g_hist[t + k * 1024] = 0u;
    if (t == 0) {
        g_ncand  = 0u;
        g_bar1   = 0u;
        g_bar2   = 0u;
        g_bar3   = 0u;
        g_encmax = 0u;
        g_encmin = 0xFFFFFFFFu;
    }
}

extern "C" void kernel_launch(void* const* d_in, const int* in_sizes, int n_in,
                              void* d_out, int out_size) {
    const float* g0   = (const float*)d_in[0];
    const float* g1   = (const float*)d_in[1];
    const float* g2   = (const float*)d_in[2];
    const float* anch = (const float*)d_in[3];
    float* out = (float*)d_out;

    cudaFuncSetAttribute(k_all, cudaFuncAttributeMaxDynamicSharedMemorySize, SM_TOTAL);
    k_all<<<FB, 1024, SM_TOTAL>>>(g0, g1, g2, anch, out);
}

// round 9
// speedup vs baseline: 1.0224x; 1.0224x over previous
#include <cuda_runtime.h>
#include <cstdint>

#define N0 6912      // 48*48*3
#define N1 27648     // 96*96*3
#define N2 110592    // 192*192*3
#define N_TOTAL 145152
#define MAX_BOXES 100

#define NBINS 4096
#define BIN_SHIFT 20
#define POSBIN0 2048          // bin of enc(+0.0)
#define CAP 2048
#define PRE 1024
#define TARGET 1024
#define FB 142                // blocks (142*1024 = 145408 >= N_TOTAL)

// ---------------- scratch (device globals; zero/const static init) -------
__device__ float4 g_box[N_TOTAL];           // written only for candidates
__device__ float  g_cls[N_TOTAL];           // written only for candidates
__device__ unsigned g_encmax = 0u;
__device__ unsigned g_encmin = 0xFFFFFFFFu;
__device__ unsigned g_hist[NBINS];          // zero-init; hist of fenc(conf) bins
__device__ unsigned g_ncand;                // zero-init
__device__ unsigned g_bar1, g_bar3;         // zero-init
__device__ unsigned long long g_cand[CAP];

// order-preserving float <-> uint32 encoding
__device__ __forceinline__ unsigned fenc(float f) {
    unsigned u = __float_as_uint(f);
    return (u & 0x80000000u) ? ~u : (u | 0x80000000u);
}
__device__ __forceinline__ float fdec(unsigned k) {
    unsigned u = (k & 0x80000000u) ? (k & 0x7FFFFFFFu) : ~k;
    return __uint_as_float(u);
}

__device__ __forceinline__ const float* lvlptr(int gi,
                                               const float* g0, const float* g1,
                                               const float* g2,
                                               int& H, int& arow, int& local) {
    if (gi < N0)           { H = 48;  arow = 2; local = gi;            return g0 + (size_t)local * 85; }
    else if (gi < N0 + N1) { H = 96;  arow = 1; local = gi - N0;       return g1 + (size_t)local * 85; }
    else                   { H = 192; arow = 0; local = gi - N0 - N1;  return g2 + (size_t)local * 85; }
}

// grid barrier: atomic arrive, volatile-poll wait
__device__ __forceinline__ void gsync(unsigned* ctr) {
    __threadfence();
    __syncthreads();
    if (threadIdx.x == 0) {
        atomicAdd(ctr, 1u);
        while (*(volatile unsigned*)ctr < FB) __nanosleep(32);
        __threadfence();
    }
    __syncthreads();
}

// register compare-exchange step for bitonic (j <= 16, via shuffle)
__device__ __forceinline__ unsigned long long cas_reg(unsigned long long v,
                                                      unsigned i, unsigned j,
                                                      unsigned k) {
    unsigned long long pv = __shfl_xor_sync(0xffffffffu, v, j);
    bool lower = (i & j) == 0u;
    bool desc  = (i & k) == 0u;
    unsigned long long mx = v > pv ? v : pv;
    unsigned long long mn = v > pv ? pv : v;
    return (lower == desc) ? mx : mn;
}

// =================== the whole pipeline in one kernel ===================
__global__ void __launch_bounds__(1024) k_all(const float* __restrict__ g0,
                                              const float* __restrict__ g1,
                                              const float* __restrict__ g2,
                                              const float* __restrict__ anch,
                                              float* __restrict__ out) {
    __shared__ __align__(16) char smem_raw[40960];   // 40 KB union
    __shared__ float s_conf[1024];
    __shared__ unsigned s_mx[32], s_mn[32];
    __shared__ unsigned s_part[32];
    __shared__ unsigned s_vcut;

    const int t    = threadIdx.x;
    const int b    = blockIdx.x;
    const int lane = t & 31;
    const int w    = t >> 5;
    const int gi0  = b * 1024 + t;
    const bool own = gi0 < N_TOTAL;

    // zero smem conf-histogram before phase A
    unsigned* sh = (unsigned*)smem_raw;   // 16 KB
    #pragma unroll
    for (int k = 0; k < 4; k++) sh[t + k * 1024] = 0u;
    __syncthreads();

    // ---------------- phase A: maxprob reduce + conf + conf-histogram -----
    // warp w owns boxes base..base+31 (level boundaries are 32-aligned).
    const int base = b * 1024 + w * 32;
    unsigned wemax = 0u, wemin = 0xFFFFFFFFu;

    if (base < N_TOTAL) {
        int H, arow, local;
        const float* p = lvlptr(base, g0, g1, g2, H, arow, local);

        #pragma unroll
        for (int kb = 0; kb < 32; kb += 8) {
            float a0[8], a1[8], a2[8];
            #pragma unroll
            for (int k = 0; k < 8; k++) {
                const float* q = p + (size_t)(kb + k) * 85;
                a0[k] = q[lane];
                a1[k] = q[32 + lane];
                a2[k] = (lane < 21) ? q[64 + lane] : -3.4e38f;
            }
            #pragma unroll
            for (int k = 0; k < 8; k++) {
                float bv = (lane >= 5) ? a0[k] : -3.4e38f;   // cp[0..26]
                bv = fmaxf(bv, a1[k]);                       // cp[27..58]
                bv = fmaxf(bv, a2[k]);                       // cp[59..79]
                unsigned ebv = __reduce_max_sync(0xffffffffu, fenc(bv));
                wemax = max(wemax, ebv);
                wemin = min(wemin, ebv);
                if (lane == 4) {
                    float cf = a0[k];                        // obj conf
                    s_conf[w * 32 + kb + k] = cf;
                    atomicAdd(&sh[fenc(cf) >> BIN_SHIFT], 1u);
                }
            }
        }
    }

    // block reduce -> global atomics
    if (lane == 0) { s_mx[w] = wemax; s_mn[w] = wemin; }
    __syncthreads();
    if (t == 0) {
        unsigned mx = s_mx[0], mn = s_mn[0];
        #pragma unroll
        for (int k = 1; k < 32; k++) {
            mx = max(mx, s_mx[k]);
            mn = min(mn, s_mn[k]);
        }
        atomicMax(&g_encmax, mx);
        atomicMin(&g_encmin, mn);
    }
    // merge conf-hist to global
    __syncthreads();
    #pragma unroll
    for (int k = 0; k < 4; k++) {
        unsigned v = sh[t + k * 1024];
        if (v) atomicAdd(&g_hist[t + k * 1024], v);
    }

    gsync(&g_bar1);   // hist + encmax/encmin final

    // ---------------- phase C: threshold (warp suffix scan on conf bins) --
    const float Mx = fdec(__ldcg(&g_encmax));
    const float Mn = fdec(__ldcg(&g_encmin));
    {
        unsigned c0 = __ldcg(&g_hist[POSBIN0 + 2 * t]);
        unsigned c1 = __ldcg(&g_hist[POSBIN0 + 2 * t + 1]);
        if (t == 0) s_vcut = 0x80000000u;   // default: all score >= +0
        unsigned arr = c0 + c1;

        unsigned s = arr;
        #pragma unroll
        for (int off = 1; off < 32; off <<= 1) {
            unsigned v = __shfl_down_sync(0xffffffffu, s, off);
            if (lane + off < 32) s += v;
        }
        if (lane == 0) s_part[w] = s;
        __syncthreads();
        if (w == 0) {
            unsigned pv = s_part[lane];
            unsigned ps = pv;
            #pragma unroll
            for (int off = 1; off < 32; off <<= 1) {
                unsigned v = __shfl_down_sync(0xffffffffu, ps, off);
                if (lane + off < 32) ps += v;
            }
            s_part[lane] = ps - pv;       // exclusive suffix over warps
        }
        __syncthreads();
        unsigned sufInc   = s + s_part[w];
        unsigned sufAfter = sufInc - arr;
        if (sufAfter < TARGET && sufInc >= TARGET) {
            unsigned binB = (sufAfter + c1 >= TARGET) ? (POSBIN0 + 2 * t + 1)
                                                      : (POSBIN0 + 2 * t);
            float A = fdec(binB << BIN_SHIFT);          // bin lower edge (conf)
            s_vcut = fenc(A * Mx);                      // exact score-value cut
        }
    }
    __syncthreads();
    const unsigned vcut = s_vcut;

    // ---------------- phase D: compact + candidate-only decode -----------
    if (own) {
        float cf = s_conf[t];
        unsigned e = fenc(fmaxf(cf * Mx, cf * Mn));
        if (e >= vcut) {
            unsigned pos = atomicAdd(&g_ncand, 1u);
            if (pos < CAP) {
                g_cand[pos] = ((unsigned long long)e << 32) |
                              (unsigned long long)(0xFFFFFFFFu - (unsigned)gi0);

                // full decode for this candidate only (L2-hot reload)
                int H, arow, local;
                const float* p = lvlptr(gi0, g0, g1, g2, H, arow, local);
                float tx = p[0], ty = p[1], tw = p[2], th = p[3];
                float best = p[5];
                int bc = 0;
                #pragma unroll 8
                for (int c = 1; c < 80; c++) {
                    float vv = p[5 + c];
                    if (vv > best) { best = vv; bc = c; }
                }

                int a    = local % 3;
                int cell = local / 3;
                int cx   = cell % H;   // W == H for all levels
                int cy   = cell / H;
                float fH = (float)H;
                float fx = (tx + (float)cx) / fH;
                float fy = (ty + (float)cy) / fH;
                float ax = anch[arow * 6 + a * 2 + 0];
                float ay = anch[arow * 6 + a * 2 + 1];
                float bw = expf(tw) * ax;
                float bh = expf(th) * ay;

                g_box[gi0] = make_float4(fx - bw * 0.5f, fy - bh * 0.5f,
                                         fx + bw * 0.5f, fy + bh * 0.5f);
                g_cls[gi0] = (float)bc;
            }
        }
    }

    // barrier: arrive-only; block 0 waits
    __threadfence();
    __syncthreads();
    if (t == 0) atomicAdd(&g_bar3, 1u);
    if (b != 0) return;
    if (t == 0) {
        while (*(volatile unsigned*)&g_bar3 < FB) __nanosleep(32);
        __threadfence();
    }
    __syncthreads();

    // ---------------- phase E (block 0): hybrid bitonic sort --------------
    unsigned long long* keys = (unsigned long long*)smem_raw;      // 16 KB
    float4* sbox  = (float4*)(smem_raw + 16384);                   // 16 KB
    float*  scls  = (float*)(smem_raw + 32768);                    // 4 KB
    float*  sarea = (float*)(smem_raw + 36864);                    // 4 KB

    const unsigned M = min(__ldcg(&g_ncand), (unsigned)CAP);
    unsigned long long a  = (t        < (int)M) ? __ldcg(&g_cand[t])        : 0ull;
    unsigned long long bk = (t + 1024 < (int)M) ? __ldcg(&g_cand[t + 1024]) : 0ull;

    #pragma unroll
    for (unsigned k = 2; k <= 32; k <<= 1) {
        #pragma unroll
        for (unsigned j = k >> 1; j > 0; j >>= 1) {
            a  = cas_reg(a,  (unsigned)t,         j, k);
            bk = cas_reg(bk, (unsigned)t + 1024u, j, k);
        }
    }
    keys[t] = a; keys[t + 1024] = bk;
    __syncthreads();

    for (unsigned k = 64; k <= CAP; k <<= 1) {
        for (unsigned j = k >> 1; j >= 32; j >>= 1) {
            #pragma unroll
            for (unsigned bb = 0; bb < 2; bb++) {
                unsigned i = (unsigned)t + bb * 1024u;
                unsigned ixj = i ^ j;
                if (ixj > i) {
                    unsigned long long x = keys[i], y = keys[ixj];
                    bool desc = ((i & k) == 0u);
                    if ((x < y) == desc) { keys[i] = y; keys[ixj] = x; }
                }
            }
            __syncthreads();
        }
        a = keys[t]; bk = keys[t + 1024];
        #pragma unroll
        for (unsigned j = 16; j > 0; j >>= 1) {
            a  = cas_reg(a,  (unsigned)t,         j, k);
            bk = cas_reg(bk, (unsigned)t + 1024u, j, k);
        }
        keys[t] = a; keys[t + 1024] = bk;
        __syncthreads();
    }

    // ---------------- phase F: prefetch top PRE boxes+areas; zero output --
    if (t < PRE && t < (int)M) {
        unsigned idx = 0xFFFFFFFFu - (unsigned)(keys[t] & 0xFFFFFFFFull);
        float4 bx = __ldcg(&g_box[idx]);
        sbox[t]  = bx;
        scls[t]  = __ldcg(&g_cls[idx]);
        sarea[t] = (bx.z - bx.x) * (bx.w - bx.y);
    }
    if (t < 601) out[t] = 0.0f;
    __syncthreads();

    // ---------------- phase G: warp 0 pipelined greedy scan ---------------
    if (t < 32) {
        float kx1[4], ky1[4], kx2[4], ky2[4], ka[4];
        int kept = 0;

        // preload r = 0
        unsigned long long key = keys[0];
        float4 c   = sbox[0];
        float  cls = scls[0];
        float  ca  = sarea[0];

        for (unsigned r = 0; r < M && kept < MAX_BOXES; r++) {
            // prefetch r+1 (hide LDS/LDG latency behind IoU work)
            unsigned nr = (r + 1 < M) ? (r + 1) : r;
            unsigned long long key_n = keys[nr];
            float4 cn; float clsn, can;
            if (nr < PRE) {
                cn = sbox[nr]; clsn = scls[nr]; can = sarea[nr];
            } else {
                unsigned idx = 0xFFFFFFFFu - (unsigned)(key_n & 0xFFFFFFFFull);
                cn   = __ldcg(&g_box[idx]);
                clsn = __ldcg(&g_cls[idx]);
                can  = (cn.z - cn.x) * (cn.w - cn.y);
            }

            unsigned senc = (unsigned)(key >> 32);
            if (senc <= 0x80000000u) break;       // best remaining score <= 0

            bool conflict = false;
            #pragma unroll
            for (int q = 0; q < 4; q++) {
                if (q * 32 + lane < kept) {
                    float iw = fmaxf(fminf(kx2[q], c.z) - fmaxf(kx1[q], c.x), 0.0f);
                    float ih = fmaxf(fminf(ky2[q], c.w) - fmaxf(ky1[q], c.y), 0.0f);
                    float inter = iw * ih;
                    float iou = inter / (ca + ka[q] - inter);
                    conflict |= (iou > 0.5f);
                }
            }
            if (__ballot_sync(0xffffffffu, conflict) == 0u) {
                int s = kept;
                #pragma unroll
                for (int q = 0; q < 4; q++) {
                    if ((s >> 5) == q && lane == (s & 31)) {
                        kx1[q] = c.x; ky1[q] = c.y;
                        kx2[q] = c.z; ky2[q] = c.w;
                        ka[q]  = ca;
                    }
                }
                if (lane == 0) {
                    out[s * 4 + 0] = c.x;
                    out[s * 4 + 1] = c.y;
                    out[s * 4 + 2] = c.z;
                    out[s * 4 + 3] = c.w;
                    out[400 + s]   = fdec(senc);
                    out[500 + s]   = cls;
                }
                kept++;
            }

            key = key_n; c = cn; cls = clsn; ca = can;
        }
        if (lane == 0) out[600] = (float)kept;
    }

    // ---------------- phase H: reset state for next call ------------------
    __syncthreads();
    #pragma unroll
    for (int k = 0; k < 4; k++) g_hist[t + k * 1024] = 0u;
    if (t == 0) {
        g_ncand  = 0u;
        g_bar1   = 0u;
        g_bar3   = 0u;
        g_encmax = 0u;
        g_encmin = 0xFFFFFFFFu;
    }
}

extern "C" void kernel_launch(void* const* d_in, const int* in_sizes, int n_in,
                              void* d_out, int out_size) {
    const float* g0   = (const float*)d_in[0];
    const float* g1   = (const float*)d_in[1];
    const float* g2   = (const float*)d_in[2];
    const float* anch = (const float*)d_in[3];
    float* out = (float*)d_out;

    k_all<<<FB, 1024>>>(g0, g1, g2, anch, out);
}